// round 1
// baseline (speedup 1.0000x reference)
#include <cuda_runtime.h>
#include <math.h>

// Problem constants
#define NTOK 8192      // B*T
#define DMODEL 1024
#define FFN 4096
#define NEXP 8
#define NPAIR (NTOK*2)
#define LB_COEF 0.01f
#define Z_COEF 0.001f

// GEMM tiling
#define BM 128
#define BN 64
#define BK 16

// ---------------- device scratch (no allocations allowed) ----------------
__device__ float g_H[(size_t)(NPAIR + 128) * FFN];   // hidden activations per (token,expert) pair
__device__ float g_probs[NTOK * NEXP];               // full softmax probs per token
__device__ float g_zsq[NTOK];                        // logsumexp^2 per token
__device__ int   g_te[NTOK * 2];                     // top-2 expert ids per token
__device__ float g_tw[NTOK * 2];                     // top-2 weights per token
__device__ int   g_pairTok[NPAIR + 128];             // token id per pair slot (grouped by expert)
__device__ float g_pairW[NPAIR + 128];               // weight per pair slot
__device__ int   g_cnt[NEXP];
__device__ int   g_off[NEXP];
__device__ int   g_cursor[NEXP];

// ---------------- kernel 0: zero y and counters ----------------
__global__ void k_zero(float* __restrict__ y) {
    size_t i = (size_t)blockIdx.x * blockDim.x + threadIdx.x;
    const size_t n4 = (size_t)NTOK * DMODEL / 4;
    float4 z = make_float4(0.f, 0.f, 0.f, 0.f);
    for (; i < n4; i += (size_t)gridDim.x * blockDim.x)
        reinterpret_cast<float4*>(y)[i] = z;
    if (blockIdx.x == 0 && threadIdx.x < NEXP) g_cnt[threadIdx.x] = 0;
}

// ---------------- kernel 1: router (one warp per token) ----------------
__global__ void __launch_bounds__(256) k_router(const float* __restrict__ x,
                                                const float* __restrict__ Wr) {
    __shared__ float sWr[DMODEL * NEXP];  // 32 KB
    int tid = threadIdx.x;
    for (int i = tid * 4; i < DMODEL * NEXP; i += blockDim.x * 4)
        *reinterpret_cast<float4*>(&sWr[i]) = *reinterpret_cast<const float4*>(&Wr[i]);
    __syncthreads();

    int warp = tid >> 5, lane = tid & 31;
    int t = blockIdx.x * 8 + warp;
    if (t >= NTOK) return;

    float acc[NEXP];
#pragma unroll
    for (int e = 0; e < NEXP; e++) acc[e] = 0.f;

    const float* xr = x + (size_t)t * DMODEL;
    for (int d = lane; d < DMODEL; d += 32) {
        float xv = xr[d];
#pragma unroll
        for (int e = 0; e < NEXP; e++) acc[e] += xv * sWr[d * NEXP + e];
    }
#pragma unroll
    for (int e = 0; e < NEXP; e++)
        for (int o = 16; o; o >>= 1) acc[e] += __shfl_xor_sync(0xffffffff, acc[e], o);

    if (lane == 0) {
        // top-2 (ties -> lowest index, matches jax top_k)
        float v0 = -1e30f; int i0 = 0;
#pragma unroll
        for (int e = 0; e < NEXP; e++) if (acc[e] > v0) { v0 = acc[e]; i0 = e; }
        float v1 = -1e30f; int i1 = 0;
#pragma unroll
        for (int e = 0; e < NEXP; e++) if (e != i0 && acc[e] > v1) { v1 = acc[e]; i1 = e; }

        // softmax over [v0, v1] (v0 is max)
        float e1v = expf(v1 - v0);
        float inv2 = 1.f / (1.f + e1v);
        float w0 = inv2, w1 = e1v * inv2;

        // full softmax + logsumexp (max = v0)
        float se = 0.f, pr[NEXP];
#pragma unroll
        for (int e = 0; e < NEXP; e++) { pr[e] = expf(acc[e] - v0); se += pr[e]; }
        float invs = 1.f / se;
#pragma unroll
        for (int e = 0; e < NEXP; e++) g_probs[t * NEXP + e] = pr[e] * invs;
        float z = v0 + logf(se);
        g_zsq[t] = z * z;

        g_te[t * 2] = i0; g_te[t * 2 + 1] = i1;
        g_tw[t * 2] = w0; g_tw[t * 2 + 1] = w1;
        atomicAdd(&g_cnt[i0], 1);
        atomicAdd(&g_cnt[i1], 1);
    }
}

// ---------------- kernel 2: deterministic reductions + aux outputs + offsets ----------------
__global__ void __launch_bounds__(1024) k_finalize(float* __restrict__ out) {
    __shared__ float red[1024];
    __shared__ float simp[NEXP];
    __shared__ float szsq;
    int tid = threadIdx.x;

    float s[NEXP];
#pragma unroll
    for (int e = 0; e < NEXP; e++) s[e] = 0.f;
    float zs = 0.f;
    for (int t = tid; t < NTOK; t += 1024) {
#pragma unroll
        for (int e = 0; e < NEXP; e++) s[e] += g_probs[t * NEXP + e];
        zs += g_zsq[t];
    }
    for (int e = 0; e < NEXP; e++) {
        red[tid] = s[e]; __syncthreads();
        for (int o = 512; o > 0; o >>= 1) { if (tid < o) red[tid] += red[tid + o]; __syncthreads(); }
        if (tid == 0) simp[e] = red[0] / (float)NTOK;
        __syncthreads();
    }
    red[tid] = zs; __syncthreads();
    for (int o = 512; o > 0; o >>= 1) { if (tid < o) red[tid] += red[tid + o]; __syncthreads(); }
    if (tid == 0) szsq = red[0];
    __syncthreads();

    if (tid == 0) {
        float lb = 0.f;
#pragma unroll
        for (int e = 0; e < NEXP; e++) lb += simp[e] * simp[e];
        lb *= (float)NEXP * LB_COEF;
        float zl = (szsq / (float)NTOK) * Z_COEF;
        float aux = lb + zl;

        float* tail = out + (size_t)NTOK * DMODEL;
        int tot = 0;
        for (int e = 0; e < NEXP; e++) tot += g_cnt[e];
        float denom = fmaxf((float)tot, 1.f);
        for (int e = 0; e < NEXP; e++) {
            tail[e] = (float)g_cnt[e];
            tail[NEXP + e] = (float)g_cnt[e] / denom;
        }
        tail[2 * NEXP] = aux;

        int o = 0;
        for (int e = 0; e < NEXP; e++) { g_off[e] = o; g_cursor[e] = o; o += g_cnt[e]; }
    }
}

// ---------------- kernel 3: scatter pairs into expert buckets ----------------
__global__ void k_scatter() {
    int t = blockIdx.x * blockDim.x + threadIdx.x;
    if (t >= NTOK) return;
#pragma unroll
    for (int k = 0; k < 2; k++) {
        int e = g_te[t * 2 + k];
        int p = atomicAdd(&g_cursor[e], 1);
        g_pairTok[p] = t;
        g_pairW[p] = g_tw[t * 2 + k];
    }
}

// ---------------- kernel 4: grouped SGEMM1: H = relu(X_g @ W1[e] + b1[e]) ----------------
__global__ void __launch_bounds__(256) k_ffn1(const float* __restrict__ x,
                                              const float* __restrict__ W1,
                                              const float* __restrict__ b1) {
    int e = blockIdx.z;
    int rows = g_cnt[e];
    int m0 = blockIdx.x * BM;
    if (m0 >= rows) return;
    int n0 = blockIdx.y * BN;
    int base = g_off[e];

    __shared__ float As[BK][BM + 4];
    __shared__ float Bs[BK][BN];
    __shared__ int   stok[BM];

    int tid = threadIdx.x;
    if (tid < BM) {
        int r = m0 + tid;
        stok[tid] = g_pairTok[base + (r < rows ? r : 0)];
    }
    __syncthreads();

    float acc[8][4];
#pragma unroll
    for (int i = 0; i < 8; i++)
#pragma unroll
        for (int j = 0; j < 4; j++) acc[i][j] = 0.f;

    const float* Wp = W1 + (size_t)e * DMODEL * FFN;
    int ty = tid >> 4, tx = tid & 15;

    for (int k0 = 0; k0 < DMODEL; k0 += BK) {
#pragma unroll
        for (int i = 0; i < 2; i++) {
            int idx = tid + i * 256;
            int r = idx >> 2;
            int c4 = (idx & 3) << 2;
            float4 v = *reinterpret_cast<const float4*>(&x[(size_t)stok[r] * DMODEL + k0 + c4]);
            As[c4 + 0][r] = v.x; As[c4 + 1][r] = v.y; As[c4 + 2][r] = v.z; As[c4 + 3][r] = v.w;
        }
        {
            int r = tid >> 4;
            int c4 = (tid & 15) << 2;
            *reinterpret_cast<float4*>(&Bs[r][c4]) =
                *reinterpret_cast<const float4*>(&Wp[(size_t)(k0 + r) * FFN + n0 + c4]);
        }
        __syncthreads();
#pragma unroll
        for (int k = 0; k < BK; k++) {
            float a[8], b[4];
            *reinterpret_cast<float4*>(a)     = *reinterpret_cast<float4*>(&As[k][ty * 8]);
            *reinterpret_cast<float4*>(a + 4) = *reinterpret_cast<float4*>(&As[k][ty * 8 + 4]);
            *reinterpret_cast<float4*>(b)     = *reinterpret_cast<float4*>(&Bs[k][tx * 4]);
#pragma unroll
            for (int i = 0; i < 8; i++)
#pragma unroll
                for (int j = 0; j < 4; j++) acc[i][j] += a[i] * b[j];
        }
        __syncthreads();
    }

    int n = n0 + tx * 4;
    float4 bb = *reinterpret_cast<const float4*>(&b1[(size_t)e * FFN + n]);
#pragma unroll
    for (int i = 0; i < 8; i++) {
        int gm = m0 + ty * 8 + i;
        if (gm < rows) {
            float4 v;
            v.x = fmaxf(acc[i][0] + bb.x, 0.f);
            v.y = fmaxf(acc[i][1] + bb.y, 0.f);
            v.z = fmaxf(acc[i][2] + bb.z, 0.f);
            v.w = fmaxf(acc[i][3] + bb.w, 0.f);
            *reinterpret_cast<float4*>(&g_H[(size_t)(base + gm) * FFN + n]) = v;
        }
    }
}

// ---------------- kernel 5: grouped SGEMM2: y += w * (H @ W2[e] + b2[e]) ----------------
__global__ void __launch_bounds__(256) k_ffn2(const float* __restrict__ W2,
                                              const float* __restrict__ b2,
                                              float* __restrict__ y) {
    int e = blockIdx.z;
    int rows = g_cnt[e];
    int m0 = blockIdx.x * BM;
    if (m0 >= rows) return;
    int n0 = blockIdx.y * BN;
    int base = g_off[e];

    __shared__ float As[BK][BM + 4];
    __shared__ float Bs[BK][BN];
    __shared__ int   stok[BM];
    __shared__ float sw[BM];

    int tid = threadIdx.x;
    if (tid < BM) {
        int r = m0 + tid;
        int rr = (r < rows ? r : 0);
        stok[tid] = g_pairTok[base + rr];
        sw[tid]   = g_pairW[base + rr];
    }
    __syncthreads();

    float acc[8][4];
#pragma unroll
    for (int i = 0; i < 8; i++)
#pragma unroll
        for (int j = 0; j < 4; j++) acc[i][j] = 0.f;

    const float* Wp = W2 + (size_t)e * FFN * DMODEL;
    int ty = tid >> 4, tx = tid & 15;

    for (int k0 = 0; k0 < FFN; k0 += BK) {
#pragma unroll
        for (int i = 0; i < 2; i++) {
            int idx = tid + i * 256;
            int r = idx >> 2;
            int c4 = (idx & 3) << 2;
            // rows beyond count read (valid, allocated) scratch; results discarded
            float4 v = *reinterpret_cast<const float4*>(
                &g_H[(size_t)(base + m0 + r) * FFN + k0 + c4]);
            As[c4 + 0][r] = v.x; As[c4 + 1][r] = v.y; As[c4 + 2][r] = v.z; As[c4 + 3][r] = v.w;
        }
        {
            int r = tid >> 4;
            int c4 = (tid & 15) << 2;
            *reinterpret_cast<float4*>(&Bs[r][c4]) =
                *reinterpret_cast<const float4*>(&Wp[(size_t)(k0 + r) * DMODEL + n0 + c4]);
        }
        __syncthreads();
#pragma unroll
        for (int k = 0; k < BK; k++) {
            float a[8], b[4];
            *reinterpret_cast<float4*>(a)     = *reinterpret_cast<float4*>(&As[k][ty * 8]);
            *reinterpret_cast<float4*>(a + 4) = *reinterpret_cast<float4*>(&As[k][ty * 8 + 4]);
            *reinterpret_cast<float4*>(b)     = *reinterpret_cast<float4*>(&Bs[k][tx * 4]);
#pragma unroll
            for (int i = 0; i < 8; i++)
#pragma unroll
                for (int j = 0; j < 4; j++) acc[i][j] += a[i] * b[j];
        }
        __syncthreads();
    }

    int n = n0 + tx * 4;
    float4 bb = *reinterpret_cast<const float4*>(&b2[(size_t)e * DMODEL + n]);
#pragma unroll
    for (int i = 0; i < 8; i++) {
        int gm = m0 + ty * 8 + i;
        if (gm < rows) {
            float w = sw[ty * 8 + i];
            int tok = stok[ty * 8 + i];
            float* yp = &y[(size_t)tok * DMODEL + n];
            atomicAdd(yp + 0, (acc[i][0] + bb.x) * w);
            atomicAdd(yp + 1, (acc[i][1] + bb.y) * w);
            atomicAdd(yp + 2, (acc[i][2] + bb.z) * w);
            atomicAdd(yp + 3, (acc[i][3] + bb.w) * w);
        }
    }
}

// ---------------- launch ----------------
extern "C" void kernel_launch(void* const* d_in, const int* in_sizes, int n_in,
                              void* d_out, int out_size) {
    const float* x  = (const float*)d_in[0];
    const float* Wr = (const float*)d_in[1];
    const float* W1 = (const float*)d_in[2];
    const float* b1 = (const float*)d_in[3];
    const float* W2 = (const float*)d_in[4];
    const float* b2 = (const float*)d_in[5];
    float* out = (float*)d_out;

    k_zero<<<2048, 256>>>(out);
    k_router<<<NTOK / 8, 256>>>(x, Wr);
    k_finalize<<<1, 1024>>>(out);
    k_scatter<<<(NTOK + 255) / 256, 256>>>();
    k_ffn1<<<dim3(NPAIR / BM, FFN / BN, NEXP), 256>>>(x, W1, b1);
    k_ffn2<<<dim3(NPAIR / BM, DMODEL / BN, NEXP), 256>>>(W2, b2, out);
}